// round 4
// baseline (speedup 1.0000x reference)
#include <cuda_runtime.h>
#include <cstdint>

// ALNNLayer fused, register-tiled (no smem), f32x2 packed math.
// Shapes: X,T,M,DT: [B=64, L=200, D=64]; alpha: [K=13]; w_v,b_t: [K,L,D];
//         w_t: [K,L,D,4]; b_v: [K,1,D]; out: [B,K,D].
// Math per (b,k,l,d):
//   kern  = exp(-relu(alpha_k) * |T - 4k|) = 2^( min(w,-w) ), w = a*T - a*4k, a = relu(alpha_k)*log2e
//   inten = kern * relu(X)
//   lat   = relu(wt0*X + wt1*DT + wt2*inten + wt3*M + 4*b_t)
//   out[b,k,d] = relu( sum_l w_v*lat + 200*b_v[k,d] )

#define KREF 13
#define LN   200
#define DN   64
#define BN   64
#define BT   8
#define LC   5
#define NCHUNK (LN / LC)        // 40
#define NBT    (BN / BT)        // 8
#define KLD    (KREF * LN * DN) // 166400

typedef unsigned long long u64;

// weight planes: [6][K*L*D] : 0 wv, 1 bt4(=4*b_t), 2..5 wt feature planes
__device__ __align__(16) float g_wplanes[6 * KLD];
// scratch[chunk][b][k][d]
__device__ __align__(16) float g_scratch[NCHUNK * BN * KREF * DN];

__device__ __forceinline__ u64 pk(float lo, float hi) {
    u64 r; asm("mov.b64 %0, {%1, %2};" : "=l"(r) : "f"(lo), "f"(hi)); return r;
}
__device__ __forceinline__ void upk(u64 v, float& lo, float& hi) {
    asm("mov.b64 {%0, %1}, %2;" : "=f"(lo), "=f"(hi) : "l"(v));
}
__device__ __forceinline__ u64 fma2(u64 a, u64 b, u64 c) {
    u64 d; asm("fma.rn.f32x2 %0, %1, %2, %3;" : "=l"(d) : "l"(a), "l"(b), "l"(c)); return d;
}
__device__ __forceinline__ u64 mul2(u64 a, u64 b) {
    u64 d; asm("mul.rn.f32x2 %0, %1, %2;" : "=l"(d) : "l"(a), "l"(b)); return d;
}
__device__ __forceinline__ float ex2f(float x) {
    float r; asm("ex2.approx.ftz.f32 %0, %1;" : "=f"(r) : "f"(x)); return r;
}

// ---------------- pre-pass: SoA weight planes ----------------
__global__ __launch_bounds__(256)
void prepack(const float* __restrict__ w_v, const float* __restrict__ b_t,
             const float* __restrict__ w_t)
{
    const int i = blockIdx.x * 256 + threadIdx.x;
    if (i >= KLD) return;
    g_wplanes[i]           = w_v[i];
    g_wplanes[KLD + i]     = 4.0f * b_t[i];
    const float4 w = *reinterpret_cast<const float4*>(w_t + (size_t)i * 4);
    g_wplanes[2 * KLD + i] = w.x;
    g_wplanes[3 * KLD + i] = w.y;
    g_wplanes[4 * KLD + i] = w.z;
    g_wplanes[5 * KLD + i] = w.w;
}

// ---------------- main ----------------
__global__ __launch_bounds__(192, 2)
void alnn_main(const float* __restrict__ X, const float* __restrict__ T,
               const float* __restrict__ M, const float* __restrict__ DT,
               const float* __restrict__ alpha)
{
    const int chunk = blockIdx.x;            // 0..39
    const int btile = blockIdx.y;            // 0..7
    const int tid   = threadIdx.x;
    const int warp  = tid >> 5;              // 0..5
    const int lane  = tid & 31;
    const int kg    = warp >> 1;             // 0..2
    const int bg    = warp & 1;              // 0..1
    const int kbase = kg * 4;                // 0,4,8
    const int kcnt  = (kg == 2) ? 5 : 4;     // k 8..12 for kg2
    const int half  = lane >> 4;             // 0/1
    const int dq    = (lane & 15) * 4;       // d-quad base
    const int bb    = btile * BT + bg * 4 + half * 2; // this lane's first b
    const int l0    = chunk * LC;

    // per-k exp constants: a = relu(alpha)*log2e ; nart = -a*4k
    float ac[5], nart[5];
    #pragma unroll
    for (int kk = 0; kk < 5; kk++) {
        const int k = kbase + kk;
        const float av = (kk < kcnt)
            ? fmaxf(__ldg(alpha + k), 0.0f) * 1.4426950408889634f : 0.0f;
        ac[kk]   = av;
        nart[kk] = -av * (4.0f * (float)k);
    }

    float4 acc[5][2];
    #pragma unroll
    for (int kk = 0; kk < 5; kk++)
        #pragma unroll
        for (int j = 0; j < 2; j++)
            acc[kk][j] = make_float4(0.f, 0.f, 0.f, 0.f);

    const size_t bstride = (size_t)LN * DN;
    const float* Xp  = X  + bb * bstride + dq;
    const float* Tp  = T  + bb * bstride + dq;
    const float* Mp  = M  + bb * bstride + dq;
    const float* DTp = DT + bb * bstride + dq;

    for (int li = 0; li < LC; li++) {
        const int l    = l0 + li;
        const int loff = l * DN;

        float4 x[2], t[2], m[2], dt[2];
        #pragma unroll
        for (int j = 0; j < 2; j++) {
            const size_t o = (size_t)j * bstride + loff;
            x[j]  = *reinterpret_cast<const float4*>(Xp  + o);
            t[j]  = *reinterpret_cast<const float4*>(Tp  + o);
            m[j]  = *reinterpret_cast<const float4*>(Mp  + o);
            dt[j] = *reinterpret_cast<const float4*>(DTp + o);
        }

        // pre-pack b-invariant-over-k operands
        u64 xp[2][2], mp[2][2], dtp[2][2], rxp[2][2];
        #pragma unroll
        for (int j = 0; j < 2; j++) {
            xp[j][0]  = pk(x[j].x, x[j].y);   xp[j][1]  = pk(x[j].z, x[j].w);
            mp[j][0]  = pk(m[j].x, m[j].y);   mp[j][1]  = pk(m[j].z, m[j].w);
            dtp[j][0] = pk(dt[j].x, dt[j].y); dtp[j][1] = pk(dt[j].z, dt[j].w);
            rxp[j][0] = pk(fmaxf(x[j].x, 0.f), fmaxf(x[j].y, 0.f));
            rxp[j][1] = pk(fmaxf(x[j].z, 0.f), fmaxf(x[j].w, 0.f));
        }

        const float* wbase = g_wplanes + (size_t)(kbase * LN + l) * DN + dq;

        #pragma unroll
        for (int kk = 0; kk < 5; kk++) {
            if (kk < kcnt) {
                const float* wp = wbase + (size_t)kk * (LN * DN);
                const float4 wv  = *reinterpret_cast<const float4*>(wp);
                const float4 bt4 = *reinterpret_cast<const float4*>(wp + KLD);
                const float4 w0  = *reinterpret_cast<const float4*>(wp + 2 * KLD);
                const float4 w1  = *reinterpret_cast<const float4*>(wp + 3 * KLD);
                const float4 w2  = *reinterpret_cast<const float4*>(wp + 4 * KLD);
                const float4 w3  = *reinterpret_cast<const float4*>(wp + 5 * KLD);
                const u64 w0p[2]  = { pk(w0.x, w0.y),  pk(w0.z, w0.w)  };
                const u64 w1p[2]  = { pk(w1.x, w1.y),  pk(w1.z, w1.w)  };
                const u64 w2p[2]  = { pk(w2.x, w2.y),  pk(w2.z, w2.w)  };
                const u64 w3p[2]  = { pk(w3.x, w3.y),  pk(w3.z, w3.w)  };
                const u64 bt4p[2] = { pk(bt4.x, bt4.y), pk(bt4.z, bt4.w) };
                const float a = ac[kk], na = nart[kk];

                #pragma unroll
                for (int j = 0; j < 2; j++) {
                    // kern per element
                    float wkx = fmaf(t[j].x, a, na);
                    float wky = fmaf(t[j].y, a, na);
                    float wkz = fmaf(t[j].z, a, na);
                    float wkw = fmaf(t[j].w, a, na);
                    const float k0 = ex2f(fminf(wkx, -wkx));
                    const float k1 = ex2f(fminf(wky, -wky));
                    const float k2 = ex2f(fminf(wkz, -wkz));
                    const float k3 = ex2f(fminf(wkw, -wkw));

                    const u64 in0 = mul2(pk(k0, k1), rxp[j][0]);
                    const u64 in1 = mul2(pk(k2, k3), rxp[j][1]);

                    const u64 s0 = fma2(w0p[0], xp[j][0],
                                   fma2(w1p[0], dtp[j][0],
                                   fma2(w2p[0], in0,
                                   fma2(w3p[0], mp[j][0], bt4p[0]))));
                    const u64 s1 = fma2(w0p[1], xp[j][1],
                                   fma2(w1p[1], dtp[j][1],
                                   fma2(w2p[1], in1,
                                   fma2(w3p[1], mp[j][1], bt4p[1]))));

                    float sx, sy, sz, sw;
                    upk(s0, sx, sy);
                    upk(s1, sz, sw);
                    acc[kk][j].x = fmaf(wv.x, fmaxf(sx, 0.f), acc[kk][j].x);
                    acc[kk][j].y = fmaf(wv.y, fmaxf(sy, 0.f), acc[kk][j].y);
                    acc[kk][j].z = fmaf(wv.z, fmaxf(sz, 0.f), acc[kk][j].z);
                    acc[kk][j].w = fmaf(wv.w, fmaxf(sw, 0.f), acc[kk][j].w);
                }
            }
        }
    }

    // store partials: scratch[chunk][b][k][d]
    #pragma unroll
    for (int kk = 0; kk < 5; kk++) {
        if (kk < kcnt) {
            #pragma unroll
            for (int j = 0; j < 2; j++) {
                float* p = g_scratch +
                    (((size_t)chunk * BN + (bb + j)) * KREF + (kbase + kk)) * DN + dq;
                *reinterpret_cast<float4*>(p) = acc[kk][j];
            }
        }
    }
}

// ---------------- finalize ----------------
__global__ __launch_bounds__(256)
void alnn_finalize(const float* __restrict__ b_v, float* __restrict__ out)
{
    const int g = blockIdx.x * 256 + threadIdx.x;   // over B*K*16 = 13312
    if (g >= BN * KREF * 16) return;
    const int dq = (g & 15) * 4;
    const int bk = g >> 4;
    const int k  = bk % KREF;

    const float* p = g_scratch + (size_t)bk * DN + dq;
    float4 s = make_float4(0.f, 0.f, 0.f, 0.f);
    #pragma unroll 8
    for (int c = 0; c < NCHUNK; c++) {
        const float4 v = *reinterpret_cast<const float4*>(p + (size_t)c * (BN * KREF * DN));
        s.x += v.x; s.y += v.y; s.z += v.z; s.w += v.w;
    }
    const float4 bv = *reinterpret_cast<const float4*>(b_v + k * DN + dq);
    float4 o;
    o.x = fmaxf(fmaf(200.f, bv.x, s.x), 0.f);
    o.y = fmaxf(fmaf(200.f, bv.y, s.y), 0.f);
    o.z = fmaxf(fmaf(200.f, bv.z, s.z), 0.f);
    o.w = fmaxf(fmaf(200.f, bv.w, s.w), 0.f);
    *reinterpret_cast<float4*>(out + (size_t)bk * DN + dq) = o;
}

extern "C" void kernel_launch(void* const* d_in, const int* in_sizes, int n_in,
                              void* d_out, int out_size)
{
    // metadata order: X, T, M, DT, alpha, w_v, w_t, b_v, b_t
    const float* X     = (const float*)d_in[0];
    const float* T     = (const float*)d_in[1];
    const float* M     = (const float*)d_in[2];
    const float* DT    = (const float*)d_in[3];
    const float* alpha = (const float*)d_in[4];
    const float* w_v   = (const float*)d_in[5];
    const float* w_t   = (const float*)d_in[6];
    const float* b_v   = (const float*)d_in[7];
    const float* b_t   = (const float*)d_in[8];
    float* out = (float*)d_out;

    prepack<<<KLD / 256, 256>>>(w_v, b_t, w_t);
    dim3 grid(NCHUNK, NBT);
    alnn_main<<<grid, 192>>>(X, T, M, DT, alpha);
    alnn_finalize<<<(BN * KREF * 16 + 255) / 256, 256>>>(b_v, out);
}

// round 5
// speedup vs baseline: 1.4627x; 1.4627x over previous
#include <cuda_runtime.h>
#include <cstdint>

// ALNNLayer fused. Warp-independent register tiling: thread = (k-group) x (8 b) x (1 d).
// Shapes: X,T,M,DT: [B=64, L=200, D=64]; alpha: [K=13]; w_v,b_t: [K,L,D];
//         w_t: [K,L,D,4]; b_v: [K,1,D]; out: [B,K,D].
// Math per (b,k,l,d):
//   kern  = exp(-relu(alpha_k)*|T-4k|) = 2^min(w,-w), w = a*T + na, a = relu(alpha)*log2e, na = -a*4k
//   inten = kern * relu(X)
//   lat   = relu(wt0*X + wt1*DT + wt2*inten + wt3*M + 4*b_t)
//   out[b,k,d] = relu( sum_l w_v*lat + 200*b_v[k,d] )

#define KREF 13
#define LN   200
#define DN   64
#define BN   64
#define BT   8
#define LC   2
#define NCH  (LN / LC)          // 100
#define NBT  (BN / BT)          // 8
#define BKD  (BN * KREF * DN)   // 53248

// scratch[chunk][b][k][d]
__device__ __align__(16) float g_scratch[NCH * BKD];

__device__ __forceinline__ float ex2f(float x) {
    float r; asm("ex2.approx.ftz.f32 %0, %1;" : "=f"(r) : "f"(x)); return r;
}

__global__ __launch_bounds__(128, 3)
void alnn_main(const float* __restrict__ X, const float* __restrict__ T,
               const float* __restrict__ M, const float* __restrict__ DT,
               const float* __restrict__ alpha,
               const float* __restrict__ w_v, const float* __restrict__ w_t,
               const float* __restrict__ b_t)
{
    const int chunk = blockIdx.x;            // 0..99
    const int btile = blockIdx.y;            // 0..7
    const int warp  = threadIdx.x >> 5;      // 0..3
    const int lane  = threadIdx.x & 31;
    const int kg    = warp >> 1;             // 0/1
    const int dg    = warp & 1;              // 0/1
    const int d     = dg * 32 + lane;        // 0..63
    const int kbase = kg ? 7 : 0;
    const int kcnt  = kg ? 6 : 7;
    const int b0    = btile * BT;
    const int l0    = chunk * LC;

    // per-k exp constants
    float a[7], na[7];
    #pragma unroll
    for (int kk = 0; kk < 7; kk++) {
        if (kk < kcnt) {
            const int k = kbase + kk;
            const float av = fmaxf(__ldg(alpha + k), 0.0f) * 1.4426950408889634f;
            a[kk]  = av;
            na[kk] = -av * (4.0f * (float)k);
        } else { a[kk] = 0.0f; na[kk] = 0.0f; }
    }

    float acc[7][BT];
    #pragma unroll
    for (int kk = 0; kk < 7; kk++)
        #pragma unroll
        for (int bi = 0; bi < BT; bi++) acc[kk][bi] = 0.0f;

    const size_t bstr = (size_t)LN * DN;

    #pragma unroll
    for (int li = 0; li < LC; li++) {
        const int l = l0 + li;
        const size_t ibase = (size_t)l * DN + d + (size_t)b0 * bstr;

        float x[BT], t[BT], m[BT], dt[BT], rx[BT];
        #pragma unroll
        for (int bi = 0; bi < BT; bi++) {
            const size_t o = ibase + (size_t)bi * bstr;
            x[bi]  = __ldg(X  + o);
            t[bi]  = __ldg(T  + o);
            m[bi]  = __ldg(M  + o);
            dt[bi] = __ldg(DT + o);
        }
        #pragma unroll
        for (int bi = 0; bi < BT; bi++) rx[bi] = fmaxf(x[bi], 0.0f);

        #pragma unroll
        for (int kk = 0; kk < 7; kk++) {
            if (kk < kcnt) {
                const size_t woff = ((size_t)(kbase + kk) * LN + l) * DN + d;
                const float  wv  = __ldg(w_v + woff);
                const float  bt4 = 4.0f * __ldg(b_t + woff);
                const float4 wt  = __ldg(reinterpret_cast<const float4*>(w_t) + woff);
                const float  ak = a[kk], nak = na[kk];

                #pragma unroll
                for (int bi = 0; bi < BT; bi++) {
                    const float w  = fmaf(t[bi], ak, nak);
                    const float e  = ex2f(fminf(w, -w));
                    const float in = e * rx[bi];
                    const float s  = fmaf(wt.x, x[bi],
                                     fmaf(wt.y, dt[bi],
                                     fmaf(wt.z, in,
                                     fmaf(wt.w, m[bi], bt4))));
                    acc[kk][bi] = fmaf(wv, fmaxf(s, 0.0f), acc[kk][bi]);
                }
            }
        }
    }

    // store partials: scratch[chunk][b][k][d]
    #pragma unroll
    for (int kk = 0; kk < 7; kk++) {
        if (kk < kcnt) {
            #pragma unroll
            for (int bi = 0; bi < BT; bi++) {
                g_scratch[((size_t)(chunk * BN + b0 + bi) * KREF + (kbase + kk)) * DN + d]
                    = acc[kk][bi];
            }
        }
    }
}

// finalize: 208 blocks x 256 thr; thread = (bk,d-quad) x chunk-group of 25
__global__ __launch_bounds__(256)
void alnn_finalize(const float* __restrict__ b_v, float* __restrict__ out)
{
    const int u  = threadIdx.x & 63;         // (bk,dq) unit within block
    const int cg = threadIdx.x >> 6;         // 0..3
    const int gu = blockIdx.x * 64 + u;      // 0..13311
    const int dq = (gu & 15) * 4;
    const int bk = gu >> 4;
    const int k  = bk % KREF;

    const float* p = g_scratch + (size_t)bk * DN + dq + (size_t)cg * 25 * BKD;
    float4 s = make_float4(0.f, 0.f, 0.f, 0.f);
    #pragma unroll
    for (int c = 0; c < 25; c++) {
        const float4 v = *reinterpret_cast<const float4*>(p + (size_t)c * BKD);
        s.x += v.x; s.y += v.y; s.z += v.z; s.w += v.w;
    }

    __shared__ float4 red[4][64];
    red[cg][u] = s;
    __syncthreads();

    if (cg == 0) {
        const float4 s1 = red[1][u], s2 = red[2][u], s3 = red[3][u];
        s.x += s1.x + s2.x + s3.x;
        s.y += s1.y + s2.y + s3.y;
        s.z += s1.z + s2.z + s3.z;
        s.w += s1.w + s2.w + s3.w;
        const float4 bv = *reinterpret_cast<const float4*>(b_v + k * DN + dq);
        float4 o;
        o.x = fmaxf(fmaf(200.f, bv.x, s.x), 0.f);
        o.y = fmaxf(fmaf(200.f, bv.y, s.y), 0.f);
        o.z = fmaxf(fmaf(200.f, bv.z, s.z), 0.f);
        o.w = fmaxf(fmaf(200.f, bv.w, s.w), 0.f);
        *reinterpret_cast<float4*>(out + (size_t)bk * DN + dq) = o;
    }
}

extern "C" void kernel_launch(void* const* d_in, const int* in_sizes, int n_in,
                              void* d_out, int out_size)
{
    // metadata order: X, T, M, DT, alpha, w_v, w_t, b_v, b_t
    const float* X     = (const float*)d_in[0];
    const float* T     = (const float*)d_in[1];
    const float* M     = (const float*)d_in[2];
    const float* DT    = (const float*)d_in[3];
    const float* alpha = (const float*)d_in[4];
    const float* w_v   = (const float*)d_in[5];
    const float* w_t   = (const float*)d_in[6];
    const float* b_v   = (const float*)d_in[7];
    const float* b_t   = (const float*)d_in[8];
    float* out = (float*)d_out;

    dim3 grid(NCH, NBT);
    alnn_main<<<grid, 128>>>(X, T, M, DT, alpha, w_v, w_t, b_t);
    alnn_finalize<<<(BN * KREF * 16) / 64, 256>>>(b_v, out);
}

// round 6
// speedup vs baseline: 1.4682x; 1.0037x over previous
#include <cuda_runtime.h>
#include <cstdint>

// ALNNLayer fused. Warp-independent register tiling: thread = (k-group) x (8 b) x (1 d).
// Shapes: X,T,M,DT: [B=64, L=200, D=64]; alpha: [K=13]; w_v,b_t: [K,L,D];
//         w_t: [K,L,D,4]; b_v: [K,1,D]; out: [B,K,D].
// Math per (b,k,l,d):
//   kern  = exp(-relu(alpha_k)*|T-4k|) = 2^min(w,-w), w = a*T + na, a = relu(alpha)*log2e, na = -a*4k
//   inten = kern * relu(X)
//   lat   = relu(wt0*X + wt1*DT + wt2*inten + wt3*M + 4*b_t)
//   out[b,k,d] = relu( sum_l w_v*lat + 200*b_v[k,d] )

#define KREF 13
#define LN   200
#define DN   64
#define BN   64
#define BT   8
#define LC   4
#define NCH  (LN / LC)          // 50
#define NBT  (BN / BT)          // 8
#define BKD  (BN * KREF * DN)   // 53248

// scratch[chunk][b][k][d]
__device__ __align__(16) float g_scratch[NCH * BKD];

__device__ __forceinline__ float ex2f(float x) {
    float r; asm("ex2.approx.ftz.f32 %0, %1;" : "=f"(r) : "f"(x)); return r;
}

__global__ __launch_bounds__(128, 3)
void alnn_main(const float* __restrict__ X, const float* __restrict__ T,
               const float* __restrict__ M, const float* __restrict__ DT,
               const float* __restrict__ alpha,
               const float* __restrict__ w_v, const float* __restrict__ w_t,
               const float* __restrict__ b_t)
{
    const int chunk = blockIdx.x;            // 0..49
    const int btile = blockIdx.y;            // 0..7
    const int warp  = threadIdx.x >> 5;      // 0..3
    const int lane  = threadIdx.x & 31;
    const int kg    = warp >> 1;             // 0/1
    const int dg    = warp & 1;              // 0/1
    const int d     = dg * 32 + lane;        // 0..63
    const int kbase = kg ? 7 : 0;
    const int kcnt  = kg ? 6 : 7;
    const int b0    = btile * BT;
    const int l0    = chunk * LC;

    // per-k exp constants
    float a[7], na[7];
    #pragma unroll
    for (int kk = 0; kk < 7; kk++) {
        if (kk < kcnt) {
            const int k = kbase + kk;
            const float av = fmaxf(__ldg(alpha + k), 0.0f) * 1.4426950408889634f;
            a[kk]  = av;
            na[kk] = -av * (4.0f * (float)k);
        } else { a[kk] = 0.0f; na[kk] = 0.0f; }
    }

    float acc[7][BT];
    #pragma unroll
    for (int kk = 0; kk < 7; kk++)
        #pragma unroll
        for (int bi = 0; bi < BT; bi++) acc[kk][bi] = 0.0f;

    const size_t bstr = (size_t)LN * DN;

    #pragma unroll
    for (int li = 0; li < LC; li++) {
        const int l = l0 + li;
        const size_t ibase = (size_t)l * DN + d + (size_t)b0 * bstr;

        float x[BT], t[BT], m[BT], dt[BT], rx[BT];
        #pragma unroll
        for (int bi = 0; bi < BT; bi++) {
            const size_t o = ibase + (size_t)bi * bstr;
            x[bi]  = __ldg(X  + o);
            t[bi]  = __ldg(T  + o);
            m[bi]  = __ldg(M  + o);
            dt[bi] = __ldg(DT + o);
        }
        #pragma unroll
        for (int bi = 0; bi < BT; bi++) rx[bi] = fmaxf(x[bi], 0.0f);

        #pragma unroll
        for (int kk = 0; kk < 7; kk++) {
            if (kk < kcnt) {
                const size_t woff = ((size_t)(kbase + kk) * LN + l) * DN + d;
                const float  wv  = __ldg(w_v + woff);
                const float  bt4 = 4.0f * __ldg(b_t + woff);
                const float4 wt  = __ldg(reinterpret_cast<const float4*>(w_t) + woff);
                const float  ak = a[kk], nak = na[kk];

                #pragma unroll
                for (int bi = 0; bi < BT; bi++) {
                    const float w  = fmaf(t[bi], ak, nak);
                    const float e  = ex2f(fminf(w, -w));
                    const float in = e * rx[bi];
                    const float s  = fmaf(wt.x, x[bi],
                                     fmaf(wt.y, dt[bi],
                                     fmaf(wt.z, in,
                                     fmaf(wt.w, m[bi], bt4))));
                    acc[kk][bi] = fmaf(wv, fmaxf(s, 0.0f), acc[kk][bi]);
                }
            }
        }
    }

    // store partials: scratch[chunk][b][k][d]
    #pragma unroll
    for (int kk = 0; kk < 7; kk++) {
        if (kk < kcnt) {
            #pragma unroll
            for (int bi = 0; bi < BT; bi++) {
                g_scratch[((size_t)(chunk * BN + b0 + bi) * KREF + (kbase + kk)) * DN + d]
                    = acc[kk][bi];
            }
        }
    }
}

// finalize: 416 blocks x 256 thr; block = 32 (bk,dq) units x 8 chunk-groups.
// 50 chunks split 7,7,6,6,6,6,6,6 across the 8 groups.
__global__ __launch_bounds__(256)
void alnn_finalize(const float* __restrict__ b_v, float* __restrict__ out)
{
    const int u  = threadIdx.x & 31;          // unit within block
    const int cg = threadIdx.x >> 5;          // 0..7
    const int gu = blockIdx.x * 32 + u;       // 0..13311
    const int dq = (gu & 15) * 4;
    const int bk = gu >> 4;
    const int k  = bk % KREF;

    const int cstart = (cg < 2) ? cg * 7 : 14 + (cg - 2) * 6;
    const int ccnt   = (cg < 2) ? 7 : 6;

    const float* p = g_scratch + (size_t)bk * DN + dq + (size_t)cstart * BKD;
    float4 s = make_float4(0.f, 0.f, 0.f, 0.f);
    #pragma unroll
    for (int c = 0; c < 7; c++) {
        if (c < ccnt) {
            const float4 v = *reinterpret_cast<const float4*>(p + (size_t)c * BKD);
            s.x += v.x; s.y += v.y; s.z += v.z; s.w += v.w;
        }
    }

    __shared__ float4 red[8][32];
    red[cg][u] = s;
    __syncthreads();

    if (cg == 0) {
        #pragma unroll
        for (int i = 1; i < 8; i++) {
            const float4 v = red[i][u];
            s.x += v.x; s.y += v.y; s.z += v.z; s.w += v.w;
        }
        const float4 bv = *reinterpret_cast<const float4*>(b_v + k * DN + dq);
        float4 o;
        o.x = fmaxf(fmaf(200.f, bv.x, s.x), 0.f);
        o.y = fmaxf(fmaf(200.f, bv.y, s.y), 0.f);
        o.z = fmaxf(fmaf(200.f, bv.z, s.z), 0.f);
        o.w = fmaxf(fmaf(200.f, bv.w, s.w), 0.f);
        *reinterpret_cast<float4*>(out + (size_t)bk * DN + dq) = o;
    }
}

extern "C" void kernel_launch(void* const* d_in, const int* in_sizes, int n_in,
                              void* d_out, int out_size)
{
    // metadata order: X, T, M, DT, alpha, w_v, w_t, b_v, b_t
    const float* X     = (const float*)d_in[0];
    const float* T     = (const float*)d_in[1];
    const float* M     = (const float*)d_in[2];
    const float* DT    = (const float*)d_in[3];
    const float* alpha = (const float*)d_in[4];
    const float* w_v   = (const float*)d_in[5];
    const float* w_t   = (const float*)d_in[6];
    const float* b_v   = (const float*)d_in[7];
    const float* b_t   = (const float*)d_in[8];
    float* out = (float*)d_out;

    dim3 grid(NCH, NBT);
    alnn_main<<<grid, 128>>>(X, T, M, DT, alpha, w_v, w_t, b_t);
    alnn_finalize<<<(BN * KREF * 16) / 32, 256>>>(b_v, out);
}

// round 7
// speedup vs baseline: 1.4877x; 1.0133x over previous
#include <cuda_runtime.h>
#include <cstdint>

// ALNNLayer fused. Register tiling thread=(k-group)x(8 b)x(1 d); L-reduction via
// fp32 atomicAdd into a 213KB L2-resident accumulator (no scratch round-trip).
// Shapes: X,T,M,DT: [B=64, L=200, D=64]; alpha: [K=13]; w_v,b_t: [K,L,D];
//         w_t: [K,L,D,4]; b_v: [K,1,D]; out: [B,K,D].
// Math per (b,k,l,d):
//   kern  = exp(-relu(alpha_k)*|T-4k|) = 2^min(w,-w), w = a*T + na, a = relu(alpha)*log2e, na = -a*4k
//   inten = kern * relu(X)
//   lat   = relu(wt0*X + wt1*DT + wt2*inten + wt3*M + 4*b_t)
//   out[b,k,d] = relu( sum_l w_v*lat + 200*b_v[k,d] )

#define KREF 13
#define LN   200
#define DN   64
#define BN   64
#define BT   8
#define LC   4
#define NCH  (LN / LC)          // 50
#define NBT  (BN / BT)          // 8
#define BKD  (BN * KREF * DN)   // 53248

// accumulator[b][k][d] — zeroed each call, atomically accumulated by main
__device__ __align__(16) float g_accum[BKD];

__device__ __forceinline__ float ex2f(float x) {
    float r; asm("ex2.approx.ftz.f32 %0, %1;" : "=f"(r) : "f"(x)); return r;
}

__global__ __launch_bounds__(256)
void alnn_zero()
{
    const int i = blockIdx.x * 256 + threadIdx.x;   // over BKD/4
    if (i < BKD / 4)
        reinterpret_cast<float4*>(g_accum)[i] = make_float4(0.f, 0.f, 0.f, 0.f);
}

__global__ __launch_bounds__(128, 3)
void alnn_main(const float* __restrict__ X, const float* __restrict__ T,
               const float* __restrict__ M, const float* __restrict__ DT,
               const float* __restrict__ alpha,
               const float* __restrict__ w_v, const float* __restrict__ w_t,
               const float* __restrict__ b_t)
{
    const int chunk = blockIdx.x;            // 0..49
    const int btile = blockIdx.y;            // 0..7
    const int warp  = threadIdx.x >> 5;      // 0..3
    const int lane  = threadIdx.x & 31;
    const int kg    = warp >> 1;             // 0/1
    const int dg    = warp & 1;              // 0/1
    const int d     = dg * 32 + lane;        // 0..63
    const int kbase = kg ? 7 : 0;
    const int kcnt  = kg ? 6 : 7;
    const int b0    = btile * BT;
    const int l0    = chunk * LC;

    // per-k exp constants
    float a[7], na[7];
    #pragma unroll
    for (int kk = 0; kk < 7; kk++) {
        if (kk < kcnt) {
            const int k = kbase + kk;
            const float av = fmaxf(__ldg(alpha + k), 0.0f) * 1.4426950408889634f;
            a[kk]  = av;
            na[kk] = -av * (4.0f * (float)k);
        } else { a[kk] = 0.0f; na[kk] = 0.0f; }
    }

    float acc[7][BT];
    #pragma unroll
    for (int kk = 0; kk < 7; kk++)
        #pragma unroll
        for (int bi = 0; bi < BT; bi++) acc[kk][bi] = 0.0f;

    const size_t bstr = (size_t)LN * DN;

    #pragma unroll
    for (int li = 0; li < LC; li++) {
        const int l = l0 + li;
        const size_t ibase = (size_t)l * DN + d + (size_t)b0 * bstr;

        float x[BT], t[BT], m[BT], dt[BT], rx[BT];
        #pragma unroll
        for (int bi = 0; bi < BT; bi++) {
            const size_t o = ibase + (size_t)bi * bstr;
            x[bi]  = __ldg(X  + o);
            t[bi]  = __ldg(T  + o);
            m[bi]  = __ldg(M  + o);
            dt[bi] = __ldg(DT + o);
        }
        #pragma unroll
        for (int bi = 0; bi < BT; bi++) rx[bi] = fmaxf(x[bi], 0.0f);

        #pragma unroll
        for (int kk = 0; kk < 7; kk++) {
            if (kk < kcnt) {
                const size_t woff = ((size_t)(kbase + kk) * LN + l) * DN + d;
                const float  wv  = __ldg(w_v + woff);
                const float  bt4 = 4.0f * __ldg(b_t + woff);
                const float4 wt  = __ldg(reinterpret_cast<const float4*>(w_t) + woff);
                const float  ak = a[kk], nak = na[kk];

                #pragma unroll
                for (int bi = 0; bi < BT; bi++) {
                    const float w  = fmaf(t[bi], ak, nak);
                    const float e  = ex2f(fminf(w, -w));
                    const float in = e * rx[bi];
                    const float s  = fmaf(wt.x, x[bi],
                                     fmaf(wt.y, dt[bi],
                                     fmaf(wt.z, in,
                                     fmaf(wt.w, m[bi], bt4))));
                    acc[kk][bi] = fmaf(wv, fmaxf(s, 0.0f), acc[kk][bi]);
                }
            }
        }
    }

    // L-reduction: fire-and-forget fp32 reductions into the L2-resident accumulator
    #pragma unroll
    for (int kk = 0; kk < 7; kk++) {
        if (kk < kcnt) {
            #pragma unroll
            for (int bi = 0; bi < BT; bi++) {
                atomicAdd(&g_accum[((size_t)(b0 + bi) * KREF + (kbase + kk)) * DN + d],
                          acc[kk][bi]);
            }
        }
    }
}

// bias + relu epilogue: 13312 threads, one float4 each
__global__ __launch_bounds__(256)
void alnn_bias(const float* __restrict__ b_v, float* __restrict__ out)
{
    const int g = blockIdx.x * 256 + threadIdx.x;   // over BKD/4 = 13312
    if (g >= BKD / 4) return;
    const int dq = (g & 15) * 4;
    const int bk = g >> 4;
    const int k  = bk % KREF;

    const float4 s  = *reinterpret_cast<const float4*>(g_accum + (size_t)bk * DN + dq);
    const float4 bv = *reinterpret_cast<const float4*>(b_v + k * DN + dq);
    float4 o;
    o.x = fmaxf(fmaf(200.f, bv.x, s.x), 0.f);
    o.y = fmaxf(fmaf(200.f, bv.y, s.y), 0.f);
    o.z = fmaxf(fmaf(200.f, bv.z, s.z), 0.f);
    o.w = fmaxf(fmaf(200.f, bv.w, s.w), 0.f);
    *reinterpret_cast<float4*>(out + (size_t)bk * DN + dq) = o;
}

extern "C" void kernel_launch(void* const* d_in, const int* in_sizes, int n_in,
                              void* d_out, int out_size)
{
    // metadata order: X, T, M, DT, alpha, w_v, w_t, b_v, b_t
    const float* X     = (const float*)d_in[0];
    const float* T     = (const float*)d_in[1];
    const float* M     = (const float*)d_in[2];
    const float* DT    = (const float*)d_in[3];
    const float* alpha = (const float*)d_in[4];
    const float* w_v   = (const float*)d_in[5];
    const float* w_t   = (const float*)d_in[6];
    const float* b_v   = (const float*)d_in[7];
    const float* b_t   = (const float*)d_in[8];
    float* out = (float*)d_out;

    alnn_zero<<<(BKD / 4 + 255) / 256, 256>>>();
    dim3 grid(NCH, NBT);
    alnn_main<<<grid, 128>>>(X, T, M, DT, alpha, w_v, w_t, b_t);
    alnn_bias<<<(BKD / 4 + 255) / 256, 256>>>(b_v, out);
}